// round 16
// baseline (speedup 1.0000x reference)
#include <cuda_runtime.h>

// DeltaEncoder: delta -> BatchNorm(1ch eval) -> Linear(1,64) broadcast ->
// LIF recurrence over the 64 output channels. Output [B,O,F,T] f32 (0/1).
// B=32, T=512, F=64, O=64. 268MB output => HBM-write-bound (~6.4TB/s).
// R16: same algorithm as R12-best, retiled to 128-thread blocks
// (b, 4 f, 128 t) -> 2048 blocks: halves per-block lifetime to shrink the
// end-of-grid drain tail where DRAM desaturates. Per-warp store pattern
// unchanged: 512B contiguous float4 __stcs per o-step, typed float4* ptr.

#define BB 32
#define TT 512
#define FF 64
#define OO 64

__global__ __launch_bounds__(128)
void delta_encoder_kernel(const float* __restrict__ in,     // [B,T,F]
                          const float* __restrict__ enc_w,  // [O]
                          const float* __restrict__ enc_b,  // [O]
                          const float* __restrict__ bn_w,
                          const float* __restrict__ bn_b,
                          const float* __restrict__ bn_mean,
                          const float* __restrict__ bn_var,
                          float* __restrict__ out)          // [B,O,F,T]
{
    // Interleaved (0.5*w, 0.5*b): h = fmaf(v, 0.5, fmaf(x, wb.x, wb.y))
    __shared__ float2 swb[OO];
    // Input tile: rows r=0..128 map to t = t0-1 .. t0+127, 4 f cols, pad to 5
    __shared__ float sx[129 * 5];

    int tid = threadIdx.x;
    if (tid < OO) {
        swb[tid] = make_float2(0.5f * enc_w[tid], 0.5f * enc_b[tid]);
    }

    // Decode block: 2048 blocks = 32 b x 16 f-groups x 4 t-quarters
    int bid = blockIdx.x;
    int b  = bid >> 6;
    int fg = (bid >> 2) & 15;
    int tq = bid & 3;
    int f0 = fg * 4;
    int t0 = tq * 128;

    // Cooperative staged load: 516 floats, 16B contiguous per row.
    #pragma unroll
    for (int j = tid; j < 129 * 4; j += 128) {
        int r = j >> 2;
        int c = j & 3;
        int t_g = t0 - 1 + r;
        if (t_g < 0) t_g = 0;            // makes delta at t=0 equal 0
        sx[r * 5 + c] = in[(b * TT + t_g) * FF + f0 + c];
    }
    __syncthreads();

    // BatchNorm constants (single channel, eval mode)
    float inv  = bn_w[0] * rsqrtf(bn_var[0] + 1e-5f);
    float mean = bn_mean[0];
    float beta = bn_b[0];

    int wid  = tid >> 5;      // 0..3 -> f = f0 + wid
    int lane = tid & 31;      // 0..31 -> t = t0 + 4*lane
    int f = f0 + wid;
    int t = t0 + lane * 4;

    float xi0 = sx[(lane * 4 + 0) * 5 + wid];
    float xi1 = sx[(lane * 4 + 1) * 5 + wid];
    float xi2 = sx[(lane * 4 + 2) * 5 + wid];
    float xi3 = sx[(lane * 4 + 3) * 5 + wid];
    float xi4 = sx[(lane * 4 + 4) * 5 + wid];

    float x0 = ((xi1 - xi0) - mean) * inv + beta;
    float x1 = ((xi2 - xi1) - mean) * inv + beta;
    float x2 = ((xi3 - xi2) - mean) * inv + beta;
    float x3 = ((xi4 - xi3) - mean) * inv + beta;

    float v0 = 0.f, v1 = 0.f, v2 = 0.f, v3 = 0.f;

    // out[((b*O + o)*F + f)*T + t]; o-stride = F*T floats = 8192 float4
    float4* op = (float4*)(out + ((b * OO) * FF + f) * TT + t);
    const int strideO4 = FF * TT / 4;

    #pragma unroll 8
    for (int o = 0; o < OO; o++) {
        float2 wb = swb[o];

        float h0 = fmaf(v0, 0.5f, fmaf(x0, wb.x, wb.y));
        float h1 = fmaf(v1, 0.5f, fmaf(x1, wb.x, wb.y));
        float h2 = fmaf(v2, 0.5f, fmaf(x2, wb.x, wb.y));
        float h3 = fmaf(v3, 0.5f, fmaf(x3, wb.x, wb.y));

        float s0 = (h0 >= 1.0f) ? 1.0f : 0.0f;
        float s1 = (h1 >= 1.0f) ? 1.0f : 0.0f;
        float s2 = (h2 >= 1.0f) ? 1.0f : 0.0f;
        float s3 = (h3 >= 1.0f) ? 1.0f : 0.0f;

        v0 = (h0 >= 1.0f) ? 0.0f : h0;
        v1 = (h1 >= 1.0f) ? 0.0f : h1;
        v2 = (h2 >= 1.0f) ? 0.0f : h2;
        v3 = (h3 >= 1.0f) ? 0.0f : h3;

        __stcs(op, make_float4(s0, s1, s2, s3));
        op += strideO4;
    }
}

extern "C" void kernel_launch(void* const* d_in, const int* in_sizes, int n_in,
                              void* d_out, int out_size) {
    const float* in      = (const float*)d_in[0];
    const float* enc_w   = (const float*)d_in[1];
    const float* enc_b   = (const float*)d_in[2];
    const float* bn_w    = (const float*)d_in[3];
    const float* bn_b    = (const float*)d_in[4];
    const float* bn_mean = (const float*)d_in[5];
    const float* bn_var  = (const float*)d_in[6];
    float* out = (float*)d_out;

    delta_encoder_kernel<<<2048, 128>>>(in, enc_w, enc_b, bn_w, bn_b,
                                        bn_mean, bn_var, out);
}

// round 17
// speedup vs baseline: 1.0358x; 1.0358x over previous
#include <cuda_runtime.h>

// DeltaEncoder: delta -> BatchNorm(1ch eval) -> Linear(1,64) broadcast ->
// LIF recurrence over the 64 output channels. Output [B,O,F,T] f32 (0/1).
// B=32, T=512, F=64, O=64. 268MB output => HBM-write-bound.
// FINAL (R8/R12 config; best measured 45.568us total, twice reproduced;
// ~6.4TB/s effective stream = ~81% of HBM3e spec):
//  - block tile (b, 8 f, 128 t): 1024 blocks x 256 threads, 4 t/thread,
//    single wave (<=1184 resident capacity)
//  - input staged through SMEM (sector-exact coalesced 32B row-chunks)
//  - interleaved float2 (0.5w, 0.5b) weights: 1 LDS.64 per o-iteration
//  - TYPED float4* store pointer (guarantees STG.128) + __stcs evict-first
//  - o-recurrence: h = fmaf(v,0.5,fmaf(x,hw,hb)); h>=1 -> s=1, v=0

#define BB 32
#define TT 512
#define FF 64
#define OO 64

__global__ __launch_bounds__(256)
void delta_encoder_kernel(const float* __restrict__ in,     // [B,T,F]
                          const float* __restrict__ enc_w,  // [O]
                          const float* __restrict__ enc_b,  // [O]
                          const float* __restrict__ bn_w,
                          const float* __restrict__ bn_b,
                          const float* __restrict__ bn_mean,
                          const float* __restrict__ bn_var,
                          float* __restrict__ out)          // [B,O,F,T]
{
    // Interleaved (0.5*w, 0.5*b): h = fmaf(v, 0.5, fmaf(x, wb.x, wb.y))
    __shared__ float2 swb[OO];
    // Input tile: rows r=0..128 map to t = t0-1 .. t0+127, 8 f cols, pad to 9
    __shared__ float sx[129 * 9];

    int tid = threadIdx.x;
    if (tid < OO) {
        swb[tid] = make_float2(0.5f * enc_w[tid], 0.5f * enc_b[tid]);
    }

    // Decode block: 1024 blocks = 32 b x 8 f-groups x 4 t-quarters
    int bid = blockIdx.x;
    int b  = bid >> 5;
    int fg = (bid >> 2) & 7;
    int tq = bid & 3;
    int f0 = fg * 8;
    int t0 = tq * 128;

    // Cooperative staged load: 1032 floats, coalesced 32B row-chunks.
    #pragma unroll
    for (int j = tid; j < 129 * 8; j += 256) {
        int r = j >> 3;
        int c = j & 7;
        int t_g = t0 - 1 + r;
        if (t_g < 0) t_g = 0;            // makes delta at t=0 equal 0
        sx[r * 9 + c] = in[(b * TT + t_g) * FF + f0 + c];
    }
    __syncthreads();

    // BatchNorm constants (single channel, eval mode)
    float inv  = bn_w[0] * rsqrtf(bn_var[0] + 1e-5f);
    float mean = bn_mean[0];
    float beta = bn_b[0];

    int wid  = tid >> 5;      // 0..7 -> f = f0 + wid
    int lane = tid & 31;      // 0..31 -> t = t0 + 4*lane
    int f = f0 + wid;
    int t = t0 + lane * 4;

    float xi0 = sx[(lane * 4 + 0) * 9 + wid];
    float xi1 = sx[(lane * 4 + 1) * 9 + wid];
    float xi2 = sx[(lane * 4 + 2) * 9 + wid];
    float xi3 = sx[(lane * 4 + 3) * 9 + wid];
    float xi4 = sx[(lane * 4 + 4) * 9 + wid];

    float x0 = ((xi1 - xi0) - mean) * inv + beta;
    float x1 = ((xi2 - xi1) - mean) * inv + beta;
    float x2 = ((xi3 - xi2) - mean) * inv + beta;
    float x3 = ((xi4 - xi3) - mean) * inv + beta;

    float v0 = 0.f, v1 = 0.f, v2 = 0.f, v3 = 0.f;

    // out[((b*O + o)*F + f)*T + t]; o-stride = F*T floats = 8192 float4
    float4* op = (float4*)(out + ((b * OO) * FF + f) * TT + t);
    const int strideO4 = FF * TT / 4;

    #pragma unroll 8
    for (int o = 0; o < OO; o++) {
        float2 wb = swb[o];

        float h0 = fmaf(v0, 0.5f, fmaf(x0, wb.x, wb.y));
        float h1 = fmaf(v1, 0.5f, fmaf(x1, wb.x, wb.y));
        float h2 = fmaf(v2, 0.5f, fmaf(x2, wb.x, wb.y));
        float h3 = fmaf(v3, 0.5f, fmaf(x3, wb.x, wb.y));

        float s0 = (h0 >= 1.0f) ? 1.0f : 0.0f;
        float s1 = (h1 >= 1.0f) ? 1.0f : 0.0f;
        float s2 = (h2 >= 1.0f) ? 1.0f : 0.0f;
        float s3 = (h3 >= 1.0f) ? 1.0f : 0.0f;

        v0 = (h0 >= 1.0f) ? 0.0f : h0;
        v1 = (h1 >= 1.0f) ? 0.0f : h1;
        v2 = (h2 >= 1.0f) ? 0.0f : h2;
        v3 = (h3 >= 1.0f) ? 0.0f : h3;

        __stcs(op, make_float4(s0, s1, s2, s3));
        op += strideO4;
    }
}

extern "C" void kernel_launch(void* const* d_in, const int* in_sizes, int n_in,
                              void* d_out, int out_size) {
    const float* in      = (const float*)d_in[0];
    const float* enc_w   = (const float*)d_in[1];
    const float* enc_b   = (const float*)d_in[2];
    const float* bn_w    = (const float*)d_in[3];
    const float* bn_b    = (const float*)d_in[4];
    const float* bn_mean = (const float*)d_in[5];
    const float* bn_var  = (const float*)d_in[6];
    float* out = (float*)d_out;

    delta_encoder_kernel<<<1024, 256>>>(in, enc_w, enc_b, bn_w, bn_b,
                                        bn_mean, bn_var, out);
}